// round 9
// baseline (speedup 1.0000x reference)
#include <cuda_runtime.h>
#include <cstdint>

// Problem constants
#define BB   16
#define CC   256
#define HWC  1024          // 32*32
#define NN   16384         // BB*HWC vectors
#define DD   8192          // num codes
#define KK   256           // code dim
#define ZELEMS (BB*CC*HWC) // 4194304

// GEMM tiling
#define BLK_M 128
#define BLK_N 64
#define BKK   32
#define TM    8
#define TN    4
#define NT_D  (DD / BLK_N)   // 128 column tiles

// Scratch (static device memory; no allocations allowed)
__device__ float  g_normE[DD];
__device__ float  g_normZ[NN];
__device__ float  g_pval[NT_D * NN];
__device__ int    g_pidx[NT_D * NN];
__device__ int    g_idx[NN];
__device__ double g_loss;

// ---------------------------------------------------------------------------
// Kernel 0: A_n = sum_c z[n,c]^2. Exact bits are argmin-irrelevant: the
// bucket boundaries of fp32(A - u) sit at half-ulp multiples of u
// independent of A's low bits (A is on-grid in its binade).
// ---------------------------------------------------------------------------
__global__ void k_normZ(const float* __restrict__ z) {
    int warp = (blockIdx.x * blockDim.x + threadIdx.x) >> 5;
    int lane = threadIdx.x & 31;
    if (warp >= NN) return;
    int b  = warp >> 10;
    int hw = warp & 1023;
    const float* base = z + (size_t)b * (CC * HWC) + hw;
    float acc = 0.f;
    #pragma unroll
    for (int i = 0; i < 8; i++) {
        float v = base[(size_t)(lane + 32 * i) * HWC];
        acc = __fadd_rn(acc, __fmul_rn(v, v));
    }
    #pragma unroll
    for (int off = 16; off; off >>= 1)
        acc = __fadd_rn(acc, __shfl_down_sync(0xffffffffu, acc, off));
    if (lane == 0) g_normZ[warp] = acc;
}

// ---------------------------------------------------------------------------
// Kernel 1: B_d = ||e_d||^2 (B < half-ulp(A) always, so fp32(A+B)=A; its
// exact bits never matter). Also zeroes the loss accumulator.
// ---------------------------------------------------------------------------
__global__ void k_norm(const float* __restrict__ e) {
    if (blockIdx.x == 0 && threadIdx.x == 0) g_loss = 0.0;
    int warp = (blockIdx.x * blockDim.x + threadIdx.x) >> 5;
    int lane = threadIdx.x & 31;
    if (warp >= DD) return;
    const float* row = e + (size_t)warp * KK;
    float s = 0.f;
    #pragma unroll
    for (int i = lane; i < KK; i += 32) {
        float v = row[i];
        s = fmaf(v, v, s);
    }
    #pragma unroll
    for (int o = 16; o; o >>= 1) s += __shfl_down_sync(0xffffffffu, s, o);
    if (lane == 0) g_normE[warp] = s;
}

// ---------------------------------------------------------------------------
// Kernel 2: full-fp32 GEMM (plain fp32 inputs, FMA accumulate — matches the
// reference CPU fp32 einsum to ~1e-9, far below the flip scale) + the
// reference's QUANTIZED dist:
//   dist = fp32( fp32(A_n + B_d) - fp32(2 * C_nd) )
// + per-tile argmin with strict-< (ascending d => first-index tie-break).
// ---------------------------------------------------------------------------
__global__ __launch_bounds__(256) void k_argmin(const float* __restrict__ z,
                                                const float* __restrict__ e) {
    __shared__ float zs[BKK][BLK_M + 4];  // [k][m]
    __shared__ float es[BKK][BLK_N + 4];  // [k][j]
    __shared__ float sval[BLK_M][17];
    __shared__ int   sidx[BLK_M][17];

    const int tid = threadIdx.x;
    const int d0  = blockIdx.x * BLK_N;
    const int m0  = blockIdx.y * BLK_M;
    const int b   = m0 >> 10;       // image index (tile never crosses images)
    const int hw0 = m0 & 1023;
    const float* zb = z + (size_t)b * (CC * HWC) + hw0;  // + c*HWC + m

    const int tx = tid & 15;   // column group: cols d0 + tx*4 .. +3
    const int ty = tid >> 4;   // row group:    rows m0 + ty*8 .. +7

    float acc[TM][TN];
    #pragma unroll
    for (int i = 0; i < TM; i++)
        #pragma unroll
        for (int j = 0; j < TN; j++) acc[i][j] = 0.f;

    for (int k0 = 0; k0 < KK; k0 += BKK) {
        // load z tile (128 rows x 32 k), coalesced along m (=hw)
        {
            int m  = tid & 127;
            int ks = tid >> 7;   // 0..1
            #pragma unroll
            for (int p = 0; p < BKK; p += 2) {
                int k = ks + p;
                zs[k][m] = zb[(size_t)(k0 + k) * HWC + m];
            }
        }
        // load e tile (64 codes x 32 k), coalesced along k
        {
            int kk = tid & 31;
            int js = tid >> 5;   // 0..7
            #pragma unroll
            for (int p = 0; p < BLK_N; p += 8) {
                int j = js + p;
                es[kk][j] = e[(size_t)(d0 + j) * KK + (k0 + kk)];
            }
        }
        __syncthreads();

        #pragma unroll
        for (int k = 0; k < BKK; k++) {
            float4 av0 = *(const float4*)&zs[k][ty * TM];
            float4 av1 = *(const float4*)&zs[k][ty * TM + 4];
            float4 bv  = *(const float4*)&es[k][tx * TN];
            float a[TM] = {av0.x, av0.y, av0.z, av0.w, av1.x, av1.y, av1.z, av1.w};
            float bb4[TN] = {bv.x, bv.y, bv.z, bv.w};
            #pragma unroll
            for (int i = 0; i < TM; i++)
                #pragma unroll
                for (int j = 0; j < TN; j++)
                    acc[i][j] = fmaf(a[i], bb4[j], acc[i][j]);
        }
        __syncthreads();
    }

    // quantized dist + per-thread argmin over its 4 columns
    float ne[TN];
    #pragma unroll
    for (int j = 0; j < TN; j++) ne[j] = g_normE[d0 + tx * TN + j];

    #pragma unroll
    for (int i = 0; i < TM; i++) {
        float A = g_normZ[m0 + ty * TM + i];
        float bvv = 3.0e38f;
        int   bj  = 0;
        #pragma unroll
        for (int j = 0; j < TN; j++) {
            float t = __fadd_rn(A, ne[j]);                       // (||z||^2 + ||e||^2)
            float s = __fsub_rn(t, __fmul_rn(2.0f, acc[i][j]));  // ... - 2*C
            if (s < bvv) { bvv = s; bj = j; }                    // strict <: first idx
        }
        sval[ty * TM + i][tx] = bvv;
        sidx[ty * TM + i][tx] = d0 + tx * TN + bj;
    }
    __syncthreads();

    // per-row min over the 16 column groups (ascending tx = ascending d)
    if (tid < BLK_M) {
        float bvv = sval[tid][0];
        int   bi  = sidx[tid][0];
        #pragma unroll
        for (int c = 1; c < 16; c++) {
            float v = sval[tid][c];
            if (v < bvv) { bvv = v; bi = sidx[tid][c]; }
        }
        g_pval[(size_t)blockIdx.x * NN + m0 + tid] = bvv;
        g_pidx[(size_t)blockIdx.x * NN + m0 + tid] = bi;
    }
}

// ---------------------------------------------------------------------------
// Kernel 3: reduce 128 column-tile partials per row -> final argmin index.
// Tie-break: smaller index wins (matches jnp.argmin first occurrence).
// ---------------------------------------------------------------------------
__global__ void k_reduce(float* __restrict__ out_idx_f) {
    int n    = blockIdx.x * 8 + (threadIdx.x >> 5);
    int lane = threadIdx.x & 31;
    float bv = 3.0e38f;
    int   bi = 0x7fffffff;
    #pragma unroll
    for (int j = lane; j < NT_D; j += 32) {
        float v = g_pval[(size_t)j * NN + n];
        int   i = g_pidx[(size_t)j * NN + n];
        if (v < bv || (v == bv && i < bi)) { bv = v; bi = i; }
    }
    #pragma unroll
    for (int o = 16; o; o >>= 1) {
        float ov = __shfl_down_sync(0xffffffffu, bv, o);
        int   oi = __shfl_down_sync(0xffffffffu, bi, o);
        if (ov < bv || (ov == bv && oi < bi)) { bv = ov; bi = oi; }
    }
    if (lane == 0) {
        g_idx[n] = bi;
        out_idx_f[n] = (float)bi;
    }
}

// ---------------------------------------------------------------------------
// Kernel 4: gather z_st (exact reference fp32 op order) + loss accumulation.
// ---------------------------------------------------------------------------
__global__ void k_gather(const float* __restrict__ z,
                         const float* __restrict__ e,
                         float* __restrict__ out_zst) {
    int i  = blockIdx.x * blockDim.x + threadIdx.x;
    int hw = i & 1023;
    int bc = i >> 10;
    int c  = bc & 255;
    int b  = bc >> 8;
    int n  = b * 1024 + hw;
    int id = g_idx[n];
    float q  = e[(size_t)id * KK + c];
    float zv = z[i];
    float t  = __fsub_rn(q, zv);
    out_zst[i] = __fadd_rn(zv, t);
    float sq = __fmul_rn(t, t);

    #pragma unroll
    for (int o = 16; o; o >>= 1) sq += __shfl_down_sync(0xffffffffu, sq, o);
    __shared__ float ws[8];
    if ((threadIdx.x & 31) == 0) ws[threadIdx.x >> 5] = sq;
    __syncthreads();
    if (threadIdx.x == 0) {
        float s = 0.f;
        #pragma unroll
        for (int w = 0; w < 8; w++) s += ws[w];
        atomicAdd(&g_loss, (double)s);
    }
}

// ---------------------------------------------------------------------------
// Kernel 5: finalize loss = 1.25 * mean((q - z)^2)
// ---------------------------------------------------------------------------
__global__ void k_loss(float* __restrict__ out_loss) {
    out_loss[0] = (float)(g_loss * (1.25 / (double)ZELEMS));
}

// ---------------------------------------------------------------------------
extern "C" void kernel_launch(void* const* d_in, const int* in_sizes, int n_in,
                              void* d_out, int out_size) {
    const float* z = (const float*)d_in[0];
    const float* e = (const float*)d_in[1];
    if (n_in >= 2 && in_sizes[0] == DD * KK && in_sizes[1] == ZELEMS) {
        z = (const float*)d_in[1];
        e = (const float*)d_in[0];
    }

    float* out      = (float*)d_out;
    float* out_zst  = out;                        // ZELEMS floats
    float* out_loss = out + (out_size - NN - 1);  // 1 float
    float* out_idx  = out + (out_size - NN);      // NN floats

    k_normZ<<<NN / 8, 256>>>(z);
    k_norm<<<DD / 8, 256>>>(e);

    dim3 g2(DD / BLK_N, NN / BLK_M);   // (128, 128)
    k_argmin<<<g2, 256>>>(z, e);

    k_reduce<<<NN / 8, 256>>>(out_idx);

    k_gather<<<ZELEMS / 256, 256>>>(z, e, out_zst);

    k_loss<<<1, 1>>>(out_loss);
}

// round 11
// speedup vs baseline: 1.9865x; 1.9865x over previous
#include <cuda_runtime.h>
#include <cuda_bf16.h>
#include <cstdint>

// Problem constants
#define BB   16
#define CC   256
#define HWC  1024
#define NN   16384          // vectors
#define DD   8192           // codes
#define KK   256            // dim
#define ZELEMS (BB*CC*HWC)

#define NT16 (DD/16)        // 512 16-code groups per row

// Scratch (static device memory)
__device__ __nv_bfloat16 g_zb[NN * KK];      // z as [n][k] bf16
__device__ __nv_bfloat16 g_eb[DD * KK];      // e as [d][k] bf16
__device__ float  g_normE[DD];
__device__ float  g_normZ[NN];
__device__ float  g_pval[(size_t)NN * NT16]; // [n][group16] coarse min
__device__ float  g_rowmin[NN];
__device__ int    g_idx[NN];
__device__ double g_loss;

// ---------------- helpers ----------------
__device__ __forceinline__ unsigned smem_u32(const void* p) {
    unsigned a;
    asm("{ .reg .u64 t; cvta.to.shared.u64 t, %1; cvt.u32.u64 %0, t; }"
        : "=r"(a) : "l"(p));
    return a;
}
__device__ __forceinline__ void ldm_x4(unsigned& r0, unsigned& r1,
                                       unsigned& r2, unsigned& r3, unsigned addr) {
    asm volatile("ldmatrix.sync.aligned.m8n8.x4.shared.b16 {%0,%1,%2,%3}, [%4];"
                 : "=r"(r0), "=r"(r1), "=r"(r2), "=r"(r3) : "r"(addr));
}
__device__ __forceinline__ void mma_bf16(float* c, const unsigned* a, const unsigned* b) {
    asm volatile(
        "mma.sync.aligned.m16n8k16.row.col.f32.bf16.bf16.f32 "
        "{%0,%1,%2,%3}, {%4,%5,%6,%7}, {%8,%9}, {%0,%1,%2,%3};"
        : "+f"(c[0]), "+f"(c[1]), "+f"(c[2]), "+f"(c[3])
        : "r"(a[0]), "r"(a[1]), "r"(a[2]), "r"(a[3]), "r"(b[0]), "r"(b[1]));
}

// ---------------------------------------------------------------------------
// Convert z [b,c,hw] fp32 -> g_zb [n=b*1024+hw][k=c] bf16 (smem transpose)
// ---------------------------------------------------------------------------
__global__ void k_convert_z(const float* __restrict__ z) {
    __shared__ float t[32][33];
    int b = blockIdx.z, hw0 = blockIdx.x * 32, c0 = blockIdx.y * 32;
    int tx = threadIdx.x, ty = threadIdx.y;
    const float* src = z + ((size_t)b * CC + c0) * HWC + hw0;
    #pragma unroll
    for (int j = 0; j < 4; j++)
        t[ty + 8 * j][tx] = src[(size_t)(ty + 8 * j) * HWC + tx];
    __syncthreads();
    __nv_bfloat16* dst = g_zb + (size_t)(b * 1024 + hw0) * KK + c0;
    #pragma unroll
    for (int j = 0; j < 4; j++)
        dst[(size_t)(ty + 8 * j) * KK + tx] = __float2bfloat16(t[tx][ty + 8 * j]);
}

__global__ void k_convert_e(const float* __restrict__ e) {
    int i = blockIdx.x * blockDim.x + threadIdx.x;
    g_eb[i] = __float2bfloat16(e[i]);
}

// ---------------------------------------------------------------------------
// A_n = sum z^2 ; B_d = ||e||^2 (exact bits argmin-irrelevant, proved R7-R9)
// ---------------------------------------------------------------------------
__global__ void k_normZ(const float* __restrict__ z) {
    int warp = (blockIdx.x * blockDim.x + threadIdx.x) >> 5;
    int lane = threadIdx.x & 31;
    if (warp >= NN) return;
    int b = warp >> 10, hw = warp & 1023;
    const float* base = z + (size_t)b * (CC * HWC) + hw;
    float acc = 0.f;
    #pragma unroll
    for (int i = 0; i < 8; i++) {
        float v = base[(size_t)(lane + 32 * i) * HWC];
        acc = __fadd_rn(acc, __fmul_rn(v, v));
    }
    #pragma unroll
    for (int o = 16; o; o >>= 1)
        acc = __fadd_rn(acc, __shfl_down_sync(0xffffffffu, acc, o));
    if (lane == 0) g_normZ[warp] = acc;
}

__global__ void k_norm(const float* __restrict__ e) {
    if (blockIdx.x == 0 && threadIdx.x == 0) g_loss = 0.0;
    int warp = (blockIdx.x * blockDim.x + threadIdx.x) >> 5;
    int lane = threadIdx.x & 31;
    if (warp >= DD) return;
    const float* row = e + (size_t)warp * KK;
    float s = 0.f;
    #pragma unroll
    for (int i = lane; i < KK; i += 32) { float v = row[i]; s = fmaf(v, v, s); }
    #pragma unroll
    for (int o = 16; o; o >>= 1) s += __shfl_down_sync(0xffffffffu, s, o);
    if (lane == 0) g_normE[warp] = s;
}

// ---------------------------------------------------------------------------
// Coarse bf16 GEMM via mma.sync (HMMA, base ISA — tcgen05 is 'a'-gated and
// unavailable at this compile target). CTA tile 128x128, BK=32, 8 warps of
// 64x32. Epilogue: per-row min of (normE - 2C) per 16-code group.
// ---------------------------------------------------------------------------
__global__ __launch_bounds__(256) void k_coarse() {
    __shared__ __nv_bfloat16 As[128][40];   // 80B row stride: ldmatrix conflict-free
    __shared__ __nv_bfloat16 Bs[128][40];
    __shared__ float s_ne[128];

    const int tid = threadIdx.x, wid = tid >> 5, lane = tid & 31;
    const int d0 = blockIdx.x * 128, m0 = blockIdx.y * 128;
    const int wm = wid >> 2, wn = wid & 3;      // warp grid 2 x 4

    float acc[4][4][4];
    #pragma unroll
    for (int mi = 0; mi < 4; mi++)
        #pragma unroll
        for (int ni = 0; ni < 4; ni++)
            #pragma unroll
            for (int q = 0; q < 4; q++) acc[mi][ni][q] = 0.f;

    for (int c = tid; c < 128; c += 256) s_ne[c] = g_normE[d0 + c];

    const unsigned aBase = smem_u32(&As[0][0]);
    const unsigned bBase = smem_u32(&Bs[0][0]);

    for (int k0 = 0; k0 < KK; k0 += 32) {
        __syncthreads();
        {
            int u = tid;
            #pragma unroll
            for (int rep = 0; rep < 2; rep++, u += 256) {
                int r = u >> 2, q = u & 3;
                *(uint4*)&As[r][q * 8] =
                    *(const uint4*)&g_zb[(size_t)(m0 + r) * KK + k0 + q * 8];
            }
            u = tid;
            #pragma unroll
            for (int rep = 0; rep < 2; rep++, u += 256) {
                int r = u >> 2, q = u & 3;
                *(uint4*)&Bs[r][q * 8] =
                    *(const uint4*)&g_eb[(size_t)(d0 + r) * KK + k0 + q * 8];
            }
        }
        __syncthreads();

        #pragma unroll
        for (int kk = 0; kk < 32; kk += 16) {
            unsigned a[4][4], b[4][2];
            #pragma unroll
            for (int mi = 0; mi < 4; mi++) {
                int row = wm * 64 + mi * 16 + (lane & 15);
                int kc  = kk + ((lane >> 4) << 3);
                ldm_x4(a[mi][0], a[mi][1], a[mi][2], a[mi][3],
                       aBase + row * 80 + kc * 2);
            }
            #pragma unroll
            for (int np = 0; np < 2; np++) {
                int row = wn * 32 + np * 16 + ((lane >> 4) << 3) + (lane & 7);
                int kc  = kk + (((lane >> 3) & 1) << 3);
                ldm_x4(b[2 * np][0], b[2 * np][1], b[2 * np + 1][0], b[2 * np + 1][1],
                       bBase + row * 80 + kc * 2);
            }
            #pragma unroll
            for (int mi = 0; mi < 4; mi++)
                #pragma unroll
                for (int ni = 0; ni < 4; ni++)
                    mma_bf16(acc[mi][ni], a[mi], b[ni]);
        }
    }

    // epilogue: per (row, 16-col group) min of ne[col] - 2*C
    const int g = lane >> 2, t = lane & 3;
    #pragma unroll
    for (int mi = 0; mi < 4; mi++) {
        #pragma unroll
        for (int gp = 0; gp < 2; gp++) {
            float lo = 3.0e38f, hi = 3.0e38f;
            #pragma unroll
            for (int h = 0; h < 2; h++) {
                int ni = gp * 2 + h;
                int colb = wn * 32 + ni * 8 + t * 2;
                float ne0 = s_ne[colb], ne1 = s_ne[colb + 1];
                lo = fminf(lo, fminf(ne0 - 2.f * acc[mi][ni][0],
                                     ne1 - 2.f * acc[mi][ni][1]));
                hi = fminf(hi, fminf(ne0 - 2.f * acc[mi][ni][2],
                                     ne1 - 2.f * acc[mi][ni][3]));
            }
            lo = fminf(lo, __shfl_xor_sync(0xffffffffu, lo, 1));
            lo = fminf(lo, __shfl_xor_sync(0xffffffffu, lo, 2));
            hi = fminf(hi, __shfl_xor_sync(0xffffffffu, hi, 1));
            hi = fminf(hi, __shfl_xor_sync(0xffffffffu, hi, 2));
            if (t == 0) {
                int gidx = (d0 >> 4) + wn * 2 + gp;
                int r0 = m0 + wm * 64 + mi * 16 + g;
                g_pval[(size_t)r0 * NT16 + gidx] = lo;
                g_pval[(size_t)(r0 + 8) * NT16 + gidx] = hi;
            }
        }
    }
}

// ---------------------------------------------------------------------------
// Per-row min over 512 coarse group-mins
// ---------------------------------------------------------------------------
__global__ void k_rowmin() {
    int n = blockIdx.x * 8 + (threadIdx.x >> 5);
    int lane = threadIdx.x & 31;
    const float* pv = g_pval + (size_t)n * NT16;
    float bv = 3.0e38f;
    #pragma unroll
    for (int j = lane; j < NT16; j += 32) bv = fminf(bv, pv[j]);
    #pragma unroll
    for (int o = 16; o; o >>= 1)
        bv = fminf(bv, __shfl_down_sync(0xffffffffu, bv, o));
    if (lane == 0) g_rowmin[n] = bv;
}

// ---------------------------------------------------------------------------
// Exact refine. bf16 coarse error bound (7-bit mantissa): per-dist
// Delta <= 2^-6 * sqrt(A) * ||e||max (~= 1.95e-3) => 2*Delta <= 6.1e-5*sqrt(A).
// cutoff = rowmin + 6.2e-5*sqrt(A) + 1.2e-4 (covers 2*Delta + bucket + noise).
// Candidates rescored with the R9-proven exact model:
//   C = fp32 FMA chain; s = fp32(fp32(A+B) - fp32(2C)); first-index ties.
// ---------------------------------------------------------------------------
__global__ __launch_bounds__(128) void k_refine(const float* __restrict__ z,
                                                const float* __restrict__ e,
                                                float* __restrict__ out_idx_f) {
    __shared__ __align__(16) float zt[KK];
    __shared__ int   s_list[512];
    __shared__ int   s_n;
    __shared__ float rv[128];
    __shared__ int   ri[128];
    __shared__ float s_bestv;
    __shared__ int   s_besti;

    const int n = blockIdx.x, tid = threadIdx.x;
    const int b = n >> 10, hw = n & 1023;

    #pragma unroll
    for (int c = tid; c < KK; c += 128)
        zt[c] = z[(size_t)b * (CC * HWC) + (size_t)c * HWC + hw];

    const float A = g_normZ[n];
    const float cutoff = g_rowmin[n] + fmaf(6.2e-5f, sqrtf(A), 1.2e-4f);

    if (tid == 0) { s_bestv = 3.0e38f; s_besti = 0x7fffffff; }
    if (tid < 32) {
        const float* pv = g_pval + (size_t)n * NT16;
        int cnt = 0;
        #pragma unroll
        for (int it = 0; it < 16; it++) {
            int t = it * 32 + tid;
            bool q = pv[t] <= cutoff;
            unsigned msk = __ballot_sync(0xffffffffu, q);
            if (q) s_list[cnt + __popc(msk & ((1u << tid) - 1u))] = t;
            cnt += __popc(msk);
        }
        if (tid == 0) s_n = cnt;
    }
    __syncthreads();
    const int ncand = s_n;

    for (int base = 0; base < ncand; base += 8) {
        int slot = tid >> 4, c = tid & 15;
        float myv = 3.0e38f; int myi = 0x7fffffff;
        if (base + slot < ncand) {
            int d = s_list[base + slot] * 16 + c;
            const float4* er = (const float4*)(e + (size_t)d * KK);
            float acc = 0.f;
            #pragma unroll 8
            for (int q = 0; q < 64; q++) {
                float4 ev = er[q];
                const float4 zv = *(const float4*)(zt + 4 * q);
                acc = fmaf(zv.x, ev.x, acc);
                acc = fmaf(zv.y, ev.y, acc);
                acc = fmaf(zv.z, ev.z, acc);
                acc = fmaf(zv.w, ev.w, acc);
            }
            float t2 = __fadd_rn(A, g_normE[d]);
            myv = __fsub_rn(t2, __fmul_rn(2.0f, acc));
            myi = d;
        }
        rv[tid] = myv; ri[tid] = myi;
        __syncthreads();
        if (tid == 0) {
            float bv = s_bestv; int bi = s_besti;
            #pragma unroll
            for (int j = 0; j < 128; j++) {
                float v = rv[j]; int i = ri[j];
                if (v < bv || (v == bv && i < bi)) { bv = v; bi = i; }
            }
            s_bestv = bv; s_besti = bi;
        }
        __syncthreads();
    }

    if (tid == 0) {
        g_idx[n] = s_besti;
        out_idx_f[n] = (float)s_besti;
    }
}

// ---------------------------------------------------------------------------
// Gather z_st (exact reference op order) + loss; finalize loss.
// ---------------------------------------------------------------------------
__global__ void k_gather(const float* __restrict__ z,
                         const float* __restrict__ e,
                         float* __restrict__ out_zst) {
    int i = blockIdx.x * blockDim.x + threadIdx.x;
    int hw = i & 1023, bc = i >> 10, c = bc & 255, b = bc >> 8;
    int n = b * 1024 + hw;
    int id = g_idx[n];
    float q = e[(size_t)id * KK + c];
    float zv = z[i];
    float t = __fsub_rn(q, zv);
    out_zst[i] = __fadd_rn(zv, t);
    float sq = __fmul_rn(t, t);
    #pragma unroll
    for (int o = 16; o; o >>= 1) sq += __shfl_down_sync(0xffffffffu, sq, o);
    __shared__ float ws[8];
    if ((threadIdx.x & 31) == 0) ws[threadIdx.x >> 5] = sq;
    __syncthreads();
    if (threadIdx.x == 0) {
        float s = 0.f;
        #pragma unroll
        for (int w = 0; w < 8; w++) s += ws[w];
        atomicAdd(&g_loss, (double)s);
    }
}

__global__ void k_loss(float* __restrict__ out_loss) {
    out_loss[0] = (float)(g_loss * (1.25 / (double)ZELEMS));
}

// ---------------------------------------------------------------------------
extern "C" void kernel_launch(void* const* d_in, const int* in_sizes, int n_in,
                              void* d_out, int out_size) {
    const float* z = (const float*)d_in[0];
    const float* e = (const float*)d_in[1];
    if (n_in >= 2 && in_sizes[0] == DD * KK && in_sizes[1] == ZELEMS) {
        z = (const float*)d_in[1];
        e = (const float*)d_in[0];
    }

    float* out      = (float*)d_out;
    float* out_zst  = out;
    float* out_loss = out + (out_size - NN - 1);
    float* out_idx  = out + (out_size - NN);

    k_convert_z<<<dim3(32, 8, 16), dim3(32, 8)>>>(z);
    k_convert_e<<<(DD * KK) / 256, 256>>>(e);
    k_normZ<<<NN / 8, 256>>>(z);
    k_norm<<<DD / 8, 256>>>(e);

    k_coarse<<<dim3(DD / 128, NN / 128), 256>>>();

    k_rowmin<<<NN / 8, 256>>>();
    k_refine<<<NN, 128>>>(z, e, out_idx);
    k_gather<<<ZELEMS / 256, 256>>>(z, e, out_zst);
    k_loss<<<1, 1>>>(out_loss);
}

// round 12
// speedup vs baseline: 2.2258x; 1.1204x over previous
#include <cuda_runtime.h>
#include <cuda_bf16.h>
#include <cstdint>

// Problem constants
#define BB   16
#define CC   256
#define HWC  1024
#define NN   16384          // vectors
#define DD   8192           // codes
#define KK   256            // dim
#define ZELEMS (BB*CC*HWC)

#define NT16 (DD/16)        // 512 16-code groups per row

// Scratch (static device memory)
__device__ __nv_bfloat16 g_zb[NN * KK];      // z as [n][k] bf16
__device__ __nv_bfloat16 g_eb[DD * KK];      // e as [d][k] bf16
__device__ float  g_normE[DD];
__device__ float  g_normZ[NN];
__device__ float  g_pval[(size_t)NN * NT16]; // [n][group16] coarse min
__device__ float  g_rowmin[NN];
__device__ int    g_idx[NN];
__device__ double g_loss;

// ---------------- helpers ----------------
__device__ __forceinline__ unsigned smem_u32(const void* p) {
    unsigned a;
    asm("{ .reg .u64 t; cvta.to.shared.u64 t, %1; cvt.u32.u64 %0, t; }"
        : "=r"(a) : "l"(p));
    return a;
}
__device__ __forceinline__ void ldm_x4(unsigned& r0, unsigned& r1,
                                       unsigned& r2, unsigned& r3, unsigned addr) {
    asm volatile("ldmatrix.sync.aligned.m8n8.x4.shared.b16 {%0,%1,%2,%3}, [%4];"
                 : "=r"(r0), "=r"(r1), "=r"(r2), "=r"(r3) : "r"(addr));
}
__device__ __forceinline__ void mma_bf16(float* c, const unsigned* a, const unsigned* b) {
    asm volatile(
        "mma.sync.aligned.m16n8k16.row.col.f32.bf16.bf16.f32 "
        "{%0,%1,%2,%3}, {%4,%5,%6,%7}, {%8,%9}, {%0,%1,%2,%3};"
        : "+f"(c[0]), "+f"(c[1]), "+f"(c[2]), "+f"(c[3])
        : "r"(a[0]), "r"(a[1]), "r"(a[2]), "r"(a[3]), "r"(b[0]), "r"(b[1]));
}
#define CP16(dst, src) \
    asm volatile("cp.async.cg.shared.global [%0], [%1], 16;" :: "r"(dst), "l"(src))
#define CP_COMMIT() asm volatile("cp.async.commit_group;" ::: "memory")
#define CP_WAIT1()  asm volatile("cp.async.wait_group 1;" ::: "memory")
#define CP_WAIT0()  asm volatile("cp.async.wait_group 0;" ::: "memory")

// ---------------------------------------------------------------------------
// Convert z [b,c,hw] fp32 -> g_zb [n=b*1024+hw][k=c] bf16 (smem transpose)
// ---------------------------------------------------------------------------
__global__ void k_convert_z(const float* __restrict__ z) {
    __shared__ float t[32][33];
    int b = blockIdx.z, hw0 = blockIdx.x * 32, c0 = blockIdx.y * 32;
    int tx = threadIdx.x, ty = threadIdx.y;
    const float* src = z + ((size_t)b * CC + c0) * HWC + hw0;
    #pragma unroll
    for (int j = 0; j < 4; j++)
        t[ty + 8 * j][tx] = src[(size_t)(ty + 8 * j) * HWC + tx];
    __syncthreads();
    __nv_bfloat16* dst = g_zb + (size_t)(b * 1024 + hw0) * KK + c0;
    #pragma unroll
    for (int j = 0; j < 4; j++)
        dst[(size_t)(ty + 8 * j) * KK + tx] = __float2bfloat16(t[tx][ty + 8 * j]);
}

__global__ void k_convert_e(const float* __restrict__ e) {
    int i = blockIdx.x * blockDim.x + threadIdx.x;
    g_eb[i] = __float2bfloat16(e[i]);
}

// ---------------------------------------------------------------------------
// A_n = sum z^2 ; B_d = ||e||^2 (exact bits argmin-irrelevant, proved R7-R9)
// ---------------------------------------------------------------------------
__global__ void k_normZ(const float* __restrict__ z) {
    int warp = (blockIdx.x * blockDim.x + threadIdx.x) >> 5;
    int lane = threadIdx.x & 31;
    if (warp >= NN) return;
    int b = warp >> 10, hw = warp & 1023;
    const float* base = z + (size_t)b * (CC * HWC) + hw;
    float acc = 0.f;
    #pragma unroll
    for (int i = 0; i < 8; i++) {
        float v = base[(size_t)(lane + 32 * i) * HWC];
        acc = __fadd_rn(acc, __fmul_rn(v, v));
    }
    #pragma unroll
    for (int o = 16; o; o >>= 1)
        acc = __fadd_rn(acc, __shfl_down_sync(0xffffffffu, acc, o));
    if (lane == 0) g_normZ[warp] = acc;
}

__global__ void k_norm(const float* __restrict__ e) {
    if (blockIdx.x == 0 && threadIdx.x == 0) g_loss = 0.0;
    int warp = (blockIdx.x * blockDim.x + threadIdx.x) >> 5;
    int lane = threadIdx.x & 31;
    if (warp >= DD) return;
    const float* row = e + (size_t)warp * KK;
    float s = 0.f;
    #pragma unroll
    for (int i = lane; i < KK; i += 32) { float v = row[i]; s = fmaf(v, v, s); }
    #pragma unroll
    for (int o = 16; o; o >>= 1) s += __shfl_down_sync(0xffffffffu, s, o);
    if (lane == 0) g_normE[warp] = s;
}

// ---------------------------------------------------------------------------
// Coarse bf16 GEMM via mma.sync HMMA with 2-stage cp.async pipeline.
// CTA tile 128x128, BK=32, 8 warps of 64x32.
// Epilogue: per-row min of (normE - 2C) per 16-code group.
// ---------------------------------------------------------------------------
#define ROWB 80                 // smem row stride bytes (conflict-free ldmatrix)
#define TILEB (128 * ROWB)      // 10240 bytes per tile per stage

__global__ __launch_bounds__(256, 2) void k_coarse() {
    __shared__ __align__(16) char As[2 * TILEB];
    __shared__ __align__(16) char Bsm[2 * TILEB];
    __shared__ float s_ne[128];

    const int tid = threadIdx.x, wid = tid >> 5, lane = tid & 31;
    const int d0 = blockIdx.x * 128, m0 = blockIdx.y * 128;
    const int wm = wid >> 2, wn = wid & 3;      // warp grid 2 x 4

    float acc[4][4][4];
    #pragma unroll
    for (int mi = 0; mi < 4; mi++)
        #pragma unroll
        for (int ni = 0; ni < 4; ni++)
            #pragma unroll
            for (int q = 0; q < 4; q++) acc[mi][ni][q] = 0.f;

    for (int c = tid; c < 128; c += 256) s_ne[c] = g_normE[d0 + c];

    const unsigned aBase = smem_u32(As);
    const unsigned bBase = smem_u32(Bsm);

    // stage copy: 512 16B chunks per tile, 2 per thread per tile
    const int cr = tid >> 2, cq = tid & 3;   // row, 16B-chunk within row
    {   // prologue: stage 0, k0 = 0
        #pragma unroll
        for (int rep = 0; rep < 2; rep++) {
            int r = cr + rep * 64;
            CP16(aBase + r * ROWB + cq * 16, &g_zb[(size_t)(m0 + r) * KK + cq * 8]);
            CP16(bBase + r * ROWB + cq * 16, &g_eb[(size_t)(d0 + r) * KK + cq * 8]);
        }
        CP_COMMIT();
    }

    for (int it = 0; it < 8; it++) {
        const int buf = it & 1;
        if (it < 7) {
            const int nbuf = 1 - buf, nk0 = (it + 1) * 32;
            #pragma unroll
            for (int rep = 0; rep < 2; rep++) {
                int r = cr + rep * 64;
                CP16(aBase + nbuf * TILEB + r * ROWB + cq * 16,
                     &g_zb[(size_t)(m0 + r) * KK + nk0 + cq * 8]);
                CP16(bBase + nbuf * TILEB + r * ROWB + cq * 16,
                     &g_eb[(size_t)(d0 + r) * KK + nk0 + cq * 8]);
            }
            CP_COMMIT();
            CP_WAIT1();
        } else {
            CP_WAIT0();
        }
        __syncthreads();

        const unsigned aB = aBase + buf * TILEB;
        const unsigned bB = bBase + buf * TILEB;
        #pragma unroll
        for (int kk = 0; kk < 32; kk += 16) {
            unsigned a[4][4], b[4][2];
            #pragma unroll
            for (int mi = 0; mi < 4; mi++) {
                int row = wm * 64 + mi * 16 + (lane & 15);
                int kc  = kk + ((lane >> 4) << 3);
                ldm_x4(a[mi][0], a[mi][1], a[mi][2], a[mi][3],
                       aB + row * ROWB + kc * 2);
            }
            #pragma unroll
            for (int np = 0; np < 2; np++) {
                int row = wn * 32 + np * 16 + ((lane >> 4) << 3) + (lane & 7);
                int kc  = kk + (((lane >> 3) & 1) << 3);
                ldm_x4(b[2 * np][0], b[2 * np][1], b[2 * np + 1][0], b[2 * np + 1][1],
                       bB + row * ROWB + kc * 2);
            }
            #pragma unroll
            for (int mi = 0; mi < 4; mi++)
                #pragma unroll
                for (int ni = 0; ni < 4; ni++)
                    mma_bf16(acc[mi][ni], a[mi], b[ni]);
        }
        __syncthreads();
    }

    // epilogue: per (row, 16-col group) min of ne[col] - 2*C
    const int g = lane >> 2, t = lane & 3;
    #pragma unroll
    for (int mi = 0; mi < 4; mi++) {
        #pragma unroll
        for (int gp = 0; gp < 2; gp++) {
            float lo = 3.0e38f, hi = 3.0e38f;
            #pragma unroll
            for (int h = 0; h < 2; h++) {
                int ni = gp * 2 + h;
                int colb = wn * 32 + ni * 8 + t * 2;
                float ne0 = s_ne[colb], ne1 = s_ne[colb + 1];
                lo = fminf(lo, fminf(ne0 - 2.f * acc[mi][ni][0],
                                     ne1 - 2.f * acc[mi][ni][1]));
                hi = fminf(hi, fminf(ne0 - 2.f * acc[mi][ni][2],
                                     ne1 - 2.f * acc[mi][ni][3]));
            }
            lo = fminf(lo, __shfl_xor_sync(0xffffffffu, lo, 1));
            lo = fminf(lo, __shfl_xor_sync(0xffffffffu, lo, 2));
            hi = fminf(hi, __shfl_xor_sync(0xffffffffu, hi, 1));
            hi = fminf(hi, __shfl_xor_sync(0xffffffffu, hi, 2));
            if (t == 0) {
                int gidx = (d0 >> 4) + wn * 2 + gp;
                int r0 = m0 + wm * 64 + mi * 16 + g;
                g_pval[(size_t)r0 * NT16 + gidx] = lo;
                g_pval[(size_t)(r0 + 8) * NT16 + gidx] = hi;
            }
        }
    }
}

// ---------------------------------------------------------------------------
// Per-row min over 512 coarse group-mins
// ---------------------------------------------------------------------------
__global__ void k_rowmin() {
    int n = blockIdx.x * 8 + (threadIdx.x >> 5);
    int lane = threadIdx.x & 31;
    const float* pv = g_pval + (size_t)n * NT16;
    float bv = 3.0e38f;
    #pragma unroll
    for (int j = lane; j < NT16; j += 32) bv = fminf(bv, pv[j]);
    #pragma unroll
    for (int o = 16; o; o >>= 1)
        bv = fminf(bv, __shfl_down_sync(0xffffffffu, bv, o));
    if (lane == 0) g_rowmin[n] = bv;
}

// ---------------------------------------------------------------------------
// Exact refine. bf16 coarse error bound (7-bit mantissa): per-dist
// Delta <= 2^-6 * sqrt(A) * ||e||max => 2*Delta <= 6.1e-5*sqrt(A).
// cutoff = rowmin + 6.2e-5*sqrt(A) + 1.2e-4 (covers 2*Delta + bucket + noise).
// Candidates rescored with the R9-proven exact model:
//   C = fp32 FMA chain; s = fp32(fp32(A+B) - fp32(2C)); first-index ties.
// ---------------------------------------------------------------------------
__global__ __launch_bounds__(128) void k_refine(const float* __restrict__ z,
                                                const float* __restrict__ e,
                                                float* __restrict__ out_idx_f) {
    __shared__ __align__(16) float zt[KK];
    __shared__ int   s_list[512];
    __shared__ int   s_n;
    __shared__ float rv[128];
    __shared__ int   ri[128];
    __shared__ float s_bestv;
    __shared__ int   s_besti;

    const int n = blockIdx.x, tid = threadIdx.x;
    const int b = n >> 10, hw = n & 1023;

    #pragma unroll
    for (int c = tid; c < KK; c += 128)
        zt[c] = z[(size_t)b * (CC * HWC) + (size_t)c * HWC + hw];

    const float A = g_normZ[n];
    const float cutoff = g_rowmin[n] + fmaf(6.2e-5f, sqrtf(A), 1.2e-4f);

    if (tid == 0) { s_bestv = 3.0e38f; s_besti = 0x7fffffff; }
    if (tid < 32) {
        const float* pv = g_pval + (size_t)n * NT16;
        int cnt = 0;
        #pragma unroll
        for (int it = 0; it < 16; it++) {
            int t = it * 32 + tid;
            bool q = pv[t] <= cutoff;
            unsigned msk = __ballot_sync(0xffffffffu, q);
            if (q) s_list[cnt + __popc(msk & ((1u << tid) - 1u))] = t;
            cnt += __popc(msk);
        }
        if (tid == 0) s_n = cnt;
    }
    __syncthreads();
    const int ncand = s_n;

    for (int base = 0; base < ncand; base += 8) {
        int slot = tid >> 4, c = tid & 15;
        float myv = 3.0e38f; int myi = 0x7fffffff;
        if (base + slot < ncand) {
            int d = s_list[base + slot] * 16 + c;
            const float4* er = (const float4*)(e + (size_t)d * KK);
            float acc = 0.f;
            #pragma unroll 8
            for (int q = 0; q < 64; q++) {
                float4 ev = er[q];
                const float4 zv = *(const float4*)(zt + 4 * q);
                acc = fmaf(zv.x, ev.x, acc);
                acc = fmaf(zv.y, ev.y, acc);
                acc = fmaf(zv.z, ev.z, acc);
                acc = fmaf(zv.w, ev.w, acc);
            }
            float t2 = __fadd_rn(A, g_normE[d]);
            myv = __fsub_rn(t2, __fmul_rn(2.0f, acc));
            myi = d;
        }
        rv[tid] = myv; ri[tid] = myi;
        __syncthreads();
        if (tid == 0) {
            float bv = s_bestv; int bi = s_besti;
            #pragma unroll
            for (int j = 0; j < 128; j++) {
                float v = rv[j]; int i = ri[j];
                if (v < bv || (v == bv && i < bi)) { bv = v; bi = i; }
            }
            s_bestv = bv; s_besti = bi;
        }
        __syncthreads();
    }

    if (tid == 0) {
        g_idx[n] = s_besti;
        out_idx_f[n] = (float)s_besti;
    }
}

// ---------------------------------------------------------------------------
// Gather z_st (exact reference op order) + loss; finalize loss.
// ---------------------------------------------------------------------------
__global__ void k_gather(const float* __restrict__ z,
                         const float* __restrict__ e,
                         float* __restrict__ out_zst) {
    int i = blockIdx.x * blockDim.x + threadIdx.x;
    int hw = i & 1023, bc = i >> 10, c = bc & 255, b = bc >> 8;
    int n = b * 1024 + hw;
    int id = g_idx[n];
    float q = e[(size_t)id * KK + c];
    float zv = z[i];
    float t = __fsub_rn(q, zv);
    out_zst[i] = __fadd_rn(zv, t);
    float sq = __fmul_rn(t, t);
    #pragma unroll
    for (int o = 16; o; o >>= 1) sq += __shfl_down_sync(0xffffffffu, sq, o);
    __shared__ float ws[8];
    if ((threadIdx.x & 31) == 0) ws[threadIdx.x >> 5] = sq;
    __syncthreads();
    if (threadIdx.x == 0) {
        float s = 0.f;
        #pragma unroll
        for (int w = 0; w < 8; w++) s += ws[w];
        atomicAdd(&g_loss, (double)s);
    }
}

__global__ void k_loss(float* __restrict__ out_loss) {
    out_loss[0] = (float)(g_loss * (1.25 / (double)ZELEMS));
}

// ---------------------------------------------------------------------------
extern "C" void kernel_launch(void* const* d_in, const int* in_sizes, int n_in,
                              void* d_out, int out_size) {
    const float* z = (const float*)d_in[0];
    const float* e = (const float*)d_in[1];
    if (n_in >= 2 && in_sizes[0] == DD * KK && in_sizes[1] == ZELEMS) {
        z = (const float*)d_in[1];
        e = (const float*)d_in[0];
    }

    float* out      = (float*)d_out;
    float* out_zst  = out;
    float* out_loss = out + (out_size - NN - 1);
    float* out_idx  = out + (out_size - NN);

    k_convert_z<<<dim3(32, 8, 16), dim3(32, 8)>>>(z);
    k_convert_e<<<(DD * KK) / 256, 256>>>(e);
    k_normZ<<<NN / 8, 256>>>(z);
    k_norm<<<DD / 8, 256>>>(e);

    k_coarse<<<dim3(DD / 128, NN / 128), 256>>>();

    k_rowmin<<<NN / 8, 256>>>();
    k_refine<<<NN, 128>>>(z, e, out_idx);
    k_gather<<<ZELEMS / 256, 256>>>(z, e, out_zst);
    k_loss<<<1, 1>>>(out_loss);
}